// round 7
// baseline (speedup 1.0000x reference)
#include <cuda_runtime.h>
#include <cstdint>

// Problem constants (fixed by reference setup_inputs).
constexpr int N_MOLS      = 2000;
constexpr int N_PER_MOL   = 64;
constexpr int PAIRS_PER_M = N_PER_MOL * (N_PER_MOL - 1);   // 4032
constexpr float CUT2      = 25.0f;                         // 5.0^2

// Output layout (flatten of reference tuple, all float32):
//   [0,    P)  : i_idx
//   [P,   2P)  : j_idx
//   [2P,  3P)  : d_ij
//   [3P,  6P)  : r_ij (row-major [P,3])
// with P = N_MOLS * PAIRS_PER_M = 8,064,000.

__global__ __launch_bounds__(256)
void neighborlist_kernel(const float* __restrict__ pos, float* __restrict__ out)
{
    __shared__ float sx[N_PER_MOL];
    __shared__ float sy[N_PER_MOL];
    __shared__ float sz[N_PER_MOL];

    const int m = blockIdx.x;
    const int t = threadIdx.x;
    const int lane = t & 31;

    if (t < N_PER_MOL) {
        const float* p = pos + (unsigned)(m * N_PER_MOL + t) * 3u;
        sx[t] = p[0];
        sy[t] = p[1];
        sz[t] = p[2];
    }
    __syncthreads();

    const unsigned P = (unsigned)N_MOLS * PAIRS_PER_M;
    float* __restrict__ out_i = out;
    float* __restrict__ out_j = out + P;
    float* __restrict__ out_d = out + 2u * P;
    float* __restrict__ out_r = out + 3u * P;

    const unsigned base   = (unsigned)m * PAIRS_PER_M;
    const float    fabase = (float)(m * N_PER_MOL);

    // One pair per thread per pass; each warp covers 32 consecutive pairs, so
    // i/j/d stores are single-line coalesced and the warp's r_ij region is a
    // 384B line-aligned block. Last pass drops whole warps only (4032 = 126*32),
    // so every active warp is full and shuffles are safe.
    for (int p = t; p < PAIRS_PER_M; p += 256) {
        const int i  = p / 63;                 // const-div -> mul/shift
        const int jr = p - i * 63;
        const int j  = jr + (jr >= i ? 1 : 0);

        const float dx = sx[j] - sx[i];
        const float dy = sy[j] - sy[i];
        const float dz = sz[j] - sz[i];
        const float q  = fmaf(dx, dx, fmaf(dy, dy, dz * dz));
        const bool  in_cut = (q <= CUT2);

        const unsigned g = base + (unsigned)p;
        out_i[g] = fabase + (float)i;
        out_j[g] = fabase + (float)j;
        out_d[g] = in_cut ? sqrtf(q) : 0.0f;

        const float rx = in_cut ? dx : 0.0f;
        const float ry = in_cut ? dy : 0.0f;
        const float rz = in_cut ? dz : 0.0f;

        // Dense repack of this warp's 96-float r_ij block via shuffles:
        // store pass s writes elements [32s, 32s+32) of the block with
        // consecutive lanes -> one 128B wavefront per pass (3 total vs 9).
        float* __restrict__ rbase = out_r + 3u * (g - (unsigned)lane);
        #pragma unroll
        for (int s = 0; s < 3; s++) {
            const int idx = 32 * s + lane;     // element within warp block
            const int k   = idx / 3;           // source lane (pair)
            const int c   = idx - 3 * k;       // component
            const float vx = __shfl_sync(0xffffffffu, rx, k);
            const float vy = __shfl_sync(0xffffffffu, ry, k);
            const float vz = __shfl_sync(0xffffffffu, rz, k);
            rbase[idx] = (c == 0) ? vx : ((c == 1) ? vy : vz);
        }
    }
}

extern "C" void kernel_launch(void* const* d_in, const int* in_sizes, int n_in,
                              void* d_out, int out_size)
{
    const float* pos = (const float*)d_in[0];
    float* out = (float*)d_out;
    neighborlist_kernel<<<N_MOLS, 256>>>(pos, out);
}

// round 8
// speedup vs baseline: 1.1145x; 1.1145x over previous
#include <cuda_runtime.h>
#include <cstdint>

// Problem constants (fixed by reference setup_inputs).
constexpr int N_MOLS      = 2000;
constexpr int N_PER_MOL   = 64;
constexpr int PAIRS_PER_M = N_PER_MOL * (N_PER_MOL - 1);   // 4032
constexpr float CUT2      = 25.0f;                         // 5.0^2

// Output layout (flatten of reference tuple, all float32):
//   [0,    P)  : i_idx
//   [P,   2P)  : j_idx
//   [2P,  3P)  : d_ij
//   [3P,  6P)  : r_ij (row-major [P,3])
// with P = N_MOLS * PAIRS_PER_M = 8,064,000.

__global__ __launch_bounds__(256)
void neighborlist_kernel(const float* __restrict__ pos, float* __restrict__ out)
{
    __shared__ float sx[N_PER_MOL];
    __shared__ float sy[N_PER_MOL];
    __shared__ float sz[N_PER_MOL];
    __shared__ float stage[8][96];   // per-warp r_ij staging (odd warps only)

    const int m    = blockIdx.x;
    const int t    = threadIdx.x;
    const int warp = t >> 5;
    const int lane = t & 31;

    if (t < N_PER_MOL) {
        const float* p = pos + (unsigned)(m * N_PER_MOL + t) * 3u;
        sx[t] = p[0];
        sy[t] = p[1];
        sz[t] = p[2];
    }
    __syncthreads();

    const unsigned P = (unsigned)N_MOLS * PAIRS_PER_M;
    float* __restrict__ out_i = out;
    float* __restrict__ out_j = out + P;
    float* __restrict__ out_d = out + 2u * P;
    float* __restrict__ out_r = out + 3u * P;

    const unsigned base   = (unsigned)m * PAIRS_PER_M;
    const float    fabase = (float)(m * N_PER_MOL);
    const bool     staged = (warp & 1);
    float* __restrict__ st = stage[warp];

    // One pair per thread per pass; each warp covers 32 consecutive pairs ->
    // i/j/d stores 1-line coalesced; the warp's r block is a 384B aligned
    // region (3 lines). 4032 mod 256 = 192 = 6 full warps, so active warps
    // are always fully populated.
    for (int p = t; p < PAIRS_PER_M; p += 256) {
        const int i  = p / 63;                 // const-div -> mul/shift
        const int jr = p - i * 63;
        const int j  = jr + (jr >= i ? 1 : 0);

        const float dx = sx[j] - sx[i];
        const float dy = sy[j] - sy[i];
        const float dz = sz[j] - sz[i];
        const float q  = fmaf(dx, dx, fmaf(dy, dy, dz * dz));
        const bool  in_cut = (q <= CUT2);

        const unsigned g = base + (unsigned)p;
        out_i[g] = fabase + (float)i;
        out_j[g] = fabase + (float)j;
        out_d[g] = in_cut ? sqrtf(q) : 0.0f;

        const float rx = in_cut ? dx : 0.0f;
        const float ry = in_cut ? dy : 0.0f;
        const float rz = in_cut ? dz : 0.0f;

        if (staged) {
            // Odd warps: stage through smem, emit 3 dense coalesced STG.
            // STS stride-3 across lanes: gcd(3,32)=1 -> conflict-free.
            st[3 * lane + 0] = rx;
            st[3 * lane + 1] = ry;
            st[3 * lane + 2] = rz;
            __syncwarp();
            float* __restrict__ rb = out_r + 3u * (g - (unsigned)lane);
            rb[lane]      = st[lane];
            rb[32 + lane] = st[32 + lane];
            rb[64 + lane] = st[64 + lane];
            __syncwarp();
        } else {
            // Even warps: direct strided stores (3 global wf per instr).
            float* __restrict__ r = out_r + 3u * g;
            r[0] = rx;
            r[1] = ry;
            r[2] = rz;
        }
    }
}

extern "C" void kernel_launch(void* const* d_in, const int* in_sizes, int n_in,
                              void* d_out, int out_size)
{
    const float* pos = (const float*)d_in[0];
    float* out = (float*)d_out;
    neighborlist_kernel<<<N_MOLS, 256>>>(pos, out);
}